// round 5
// baseline (speedup 1.0000x reference)
#include <cuda_runtime.h>
#include <math.h>

#define B_ 64
#define T_ 512
#define H_ 256
#define G_ 1024
#define BH_ (B_*H_)

// ---------------- static device scratch (no allocations) ----------------
__device__ float g_x [(size_t)T_*B_*256];   // x,  row m = t*64+b
__device__ float g_gx[(size_t)T_*B_*G_];    // gx, row m = t*64+b
__device__ float g_h [(size_t)(T_+1)*BH_];  // h history [(T+1), B, H]
__device__ float g_c [(size_t)(T_+1)*BH_];  // c history

typedef unsigned long long u64;
typedef unsigned int u32;

// ---------------- f32x2 helpers ----------------
__device__ __forceinline__ u64 fma2(u64 a, u64 b, u64 c){
    u64 d; asm("fma.rn.f32x2 %0, %1, %2, %3;" : "=l"(d) : "l"(a), "l"(b), "l"(c)); return d;
}
__device__ __forceinline__ u64 pack2(float x, float y){
    u64 d; asm("mov.b64 %0, {%1, %2};" : "=l"(d)
               : "r"(__float_as_uint(x)), "r"(__float_as_uint(y))); return d;
}
__device__ __forceinline__ float2 unp2(u64 v){
    u32 lo, hi; asm("mov.b64 {%0, %1}, %2;" : "=r"(lo), "=r"(hi) : "l"(v));
    return make_float2(__uint_as_float(lo), __uint_as_float(hi));
}
__device__ __forceinline__ float sigm(float x){ return 1.0f/(1.0f + __expf(-x)); }

__device__ __forceinline__ void st_cluster_f32(u32 saddr, int rank, float v){
    u32 r;
    asm volatile("mapa.shared::cluster.u32 %0, %1, %2;" : "=r"(r) : "r"(saddr), "r"(rank));
    asm volatile("st.shared::cluster.f32 [%0], %1;" :: "r"(r), "f"(v));
}

// ---------------- mbarrier helpers (cluster scope) ----------------
__device__ __forceinline__ void mbar_init(u32 a, u32 cnt){
    asm volatile("mbarrier.init.shared.b64 [%0], %1;" :: "r"(a), "r"(cnt) : "memory");
}
__device__ __forceinline__ void mbar_arrive_remote(u32 a, u32 rank){
    u32 r;
    asm volatile("mapa.shared::cluster.u32 %0, %1, %2;" : "=r"(r) : "r"(a), "r"(rank));
    asm volatile("mbarrier.arrive.release.cluster.shared::cluster.b64 _, [%0];"
                 :: "r"(r) : "memory");
}
__device__ __forceinline__ void mbar_wait(u32 a, u32 par){
    u32 done;
    asm volatile("{\n\t.reg .pred p;\n\t"
        "mbarrier.try_wait.parity.acquire.cluster.shared::cta.b64 p, [%1], %2;\n\t"
        "selp.b32 %0,1,0,p;\n\t}"
        : "=r"(done) : "r"(a), "r"(par) : "memory");
    while(!done){
        asm volatile("{\n\t.reg .pred p;\n\t"
            "mbarrier.try_wait.parity.acquire.cluster.shared::cta.b64 p, [%1], %2, 0x989680;\n\t"
            "selp.b32 %0,1,0,p;\n\t}"
            : "=r"(done) : "r"(a), "r"(par) : "memory");
    }
}

#define CARRIVE() asm volatile("barrier.cluster.arrive.aligned;" ::: "memory")
#define CWAIT()   asm volatile("barrier.cluster.wait.aligned;"   ::: "memory")

// ---------------- embedding gather + mean + concat ----------------
__global__ __launch_bounds__(128)
void embed_kernel(const int* __restrict__ node, const int* __restrict__ rel,
                  const float* __restrict__ emb)
{
    int pos  = blockIdx.x*4 + (threadIdx.x >> 5);   // pos = b*T + t
    int lane = threadIdx.x & 31;
    int b = pos >> 9, t = pos & 511;
    const float4* E = (const float4*)emb;
    int n0 = __ldg(&node[pos*2+0]);
    int n1 = __ldg(&node[pos*2+1]);
    int r0 = __ldg(&rel[pos*3+0]);
    int r1 = __ldg(&rel[pos*3+1]);
    int r2 = __ldg(&rel[pos*3+2]);
    float4 e0 = __ldg(&E[(size_t)n0*32 + lane]);
    float4 e1 = __ldg(&E[(size_t)n1*32 + lane]);
    float4 f0 = __ldg(&E[(size_t)r0*32 + lane]);
    float4 f1 = __ldg(&E[(size_t)r1*32 + lane]);
    float4 f2 = __ldg(&E[(size_t)r2*32 + lane]);
    float4 nv = make_float4(0.5f*(e0.x+e1.x), 0.5f*(e0.y+e1.y),
                            0.5f*(e0.z+e1.z), 0.5f*(e0.w+e1.w));
    const float th = (1.0f/3.0f);
    float4 rv = make_float4(th*(f0.x+f1.x+f2.x), th*(f0.y+f1.y+f2.y),
                            th*(f0.z+f1.z+f2.z), th*(f0.w+f1.w+f2.w));
    float4* xr = (float4*)(g_x + ((size_t)t*B_ + b)*256);
    xr[lane]      = nv;
    xr[32 + lane] = rv;
}

// ---------------- SGEMM (NT): C[M,N] = A[M,K] * Bw[N,K]^T (+ bias[N]) ----------------
// 128x128 tile, BK=16, 256 threads, reg double-buffer, conflict-free B mapping:
// thread (tx,ty) owns cols {32j+2tx, 32j+2tx+1} j=0..3, rows ty*8..ty*8+7.
__global__ __launch_bounds__(256, 2)
void sgemm_nt(const float* __restrict__ A, const float* __restrict__ Bw,
              const float* __restrict__ bias, float* __restrict__ C,
              int M, int N, int K)
{
    __shared__ __align__(16) float As[16][128];
    __shared__ __align__(16) float Bs[16][128];
    int tid = threadIdx.x;
    int m0 = blockIdx.y * 128;
    int n0 = blockIdx.x * 128;
    int tx = tid & 15, ty = tid >> 4;

    int r0_ = tid & 127,        kq0 = (tid >> 7);        // 0..1
    int r1_ = r0_,              kq1 = kq0 + 2;           // 2..3

    u64 acc[8][4];
#pragma unroll
    for(int i=0;i<8;i++)
#pragma unroll
        for(int j=0;j<4;j++) acc[i][j] = 0ull;

    float4 av0, av1, bv0, bv1;
    // prologue fetch tile 0
    av0 = __ldg((const float4*)(A  + (size_t)(m0+r0_)*K + kq0*4));
    av1 = __ldg((const float4*)(A  + (size_t)(m0+r1_)*K + kq1*4));
    bv0 = __ldg((const float4*)(Bw + (size_t)(n0+r0_)*K + kq0*4));
    bv1 = __ldg((const float4*)(Bw + (size_t)(n0+r1_)*K + kq1*4));
    As[kq0*4+0][r0_]=av0.x; As[kq0*4+1][r0_]=av0.y; As[kq0*4+2][r0_]=av0.z; As[kq0*4+3][r0_]=av0.w;
    As[kq1*4+0][r1_]=av1.x; As[kq1*4+1][r1_]=av1.y; As[kq1*4+2][r1_]=av1.z; As[kq1*4+3][r1_]=av1.w;
    Bs[kq0*4+0][r0_]=bv0.x; Bs[kq0*4+1][r0_]=bv0.y; Bs[kq0*4+2][r0_]=bv0.z; Bs[kq0*4+3][r0_]=bv0.w;
    Bs[kq1*4+0][r1_]=bv1.x; Bs[kq1*4+1][r1_]=bv1.y; Bs[kq1*4+2][r1_]=bv1.z; Bs[kq1*4+3][r1_]=bv1.w;
    __syncthreads();

    for(int kt=0; kt<K; kt+=16){
        bool more = (kt+16 < K);
        if(more){
            av0 = __ldg((const float4*)(A  + (size_t)(m0+r0_)*K + kt+16 + kq0*4));
            av1 = __ldg((const float4*)(A  + (size_t)(m0+r1_)*K + kt+16 + kq1*4));
            bv0 = __ldg((const float4*)(Bw + (size_t)(n0+r0_)*K + kt+16 + kq0*4));
            bv1 = __ldg((const float4*)(Bw + (size_t)(n0+r1_)*K + kt+16 + kq1*4));
        }
#pragma unroll
        for(int k=0;k<16;k++){
            float4 a0 = *(const float4*)&As[k][ty*8];
            float4 a1 = *(const float4*)&As[k][ty*8+4];
            u64 b0 = *(const u64*)&Bs[k][tx*2];
            u64 b1 = *(const u64*)&Bs[k][tx*2 + 32];
            u64 b2 = *(const u64*)&Bs[k][tx*2 + 64];
            u64 b3 = *(const u64*)&Bs[k][tx*2 + 96];
            float af[8] = {a0.x,a0.y,a0.z,a0.w,a1.x,a1.y,a1.z,a1.w};
#pragma unroll
            for(int i=0;i<8;i++){
                u64 aa = pack2(af[i], af[i]);
                acc[i][0] = fma2(aa, b0, acc[i][0]);
                acc[i][1] = fma2(aa, b1, acc[i][1]);
                acc[i][2] = fma2(aa, b2, acc[i][2]);
                acc[i][3] = fma2(aa, b3, acc[i][3]);
            }
        }
        if(more){
            __syncthreads();
            As[kq0*4+0][r0_]=av0.x; As[kq0*4+1][r0_]=av0.y; As[kq0*4+2][r0_]=av0.z; As[kq0*4+3][r0_]=av0.w;
            As[kq1*4+0][r1_]=av1.x; As[kq1*4+1][r1_]=av1.y; As[kq1*4+2][r1_]=av1.z; As[kq1*4+3][r1_]=av1.w;
            Bs[kq0*4+0][r0_]=bv0.x; Bs[kq0*4+1][r0_]=bv0.y; Bs[kq0*4+2][r0_]=bv0.z; Bs[kq0*4+3][r0_]=bv0.w;
            Bs[kq1*4+0][r1_]=bv1.x; Bs[kq1*4+1][r1_]=bv1.y; Bs[kq1*4+2][r1_]=bv1.z; Bs[kq1*4+3][r1_]=bv1.w;
            __syncthreads();
        }
    }
#pragma unroll
    for(int i=0;i<8;i++){
        float* cp = C + (size_t)(m0 + ty*8 + i)*N + n0;
#pragma unroll
        for(int j=0;j<4;j++){
            float2 v = unp2(acc[i][j]);
            int col = 32*j + 2*tx;
            if(bias){
                v.x += __ldg(&bias[n0 + col    ]);
                v.y += __ldg(&bias[n0 + col + 1]);
            }
            *(float2*)(cp + col) = v;
        }
    }
}

// ---------------- serial tree-LSTM scan (p2p mbarrier sync) ----------------
// 16 clusters x 8 CTAs. Cluster c: batches [4c,4c+4). CTA rank r: units [32r,32r+32).
__global__ __launch_bounds__(256, 1) __cluster_dims__(8, 1, 1)
void scan_kernel(const int* __restrict__ father, const float* __restrict__ mask,
                 const float* __restrict__ W_hh, const float* __restrict__ b_hh,
                 float* __restrict__ out)
{
    __shared__ __align__(16) float sh[4*272];       // prefetched-h staging (padded)
    __shared__ __align__(16) float fbuf[3][4*272];  // DSMEM fresh-h ring
    __shared__ float s_gates[4*128];
    __shared__ int   s_flag[2][4];                  // 0=OLD 1=SEMI 2=FRESH per batch
    __shared__ __align__(8) u64 mb_full[3];         // count-8 full barriers

    int tid  = threadIdx.x;
    int rank = blockIdx.x & 7;
    int cid  = blockIdx.x >> 3;
    int u0   = rank * 32;
    int kidx = tid & 7;
    int rg   = tid >> 3;

    u32 mbF = (u32)__cvta_generic_to_shared(&mb_full[0]);

    // register-resident W_hh slice: 4 gate rows x 32 K-floats (16 u64 each)
    u64   w2[64];
    float bh[4];
    int   grow_[4];
#pragma unroll
    for(int rj=0; rj<4; rj++){
        int lr   = rg*4 + rj;
        int grow = (lr>>5)*256 + u0 + (lr&31);
        grow_[rj] = grow;
        bh[rj]    = __ldg(&b_hh[grow]);
        const u64* Wp = (const u64*)(W_hh + (size_t)grow*256 + kidx*32);
#pragma unroll
        for(int i=0;i<16;i++) w2[rj*16+i] = __ldg(&Wp[i]);
    }

    int sb   = tid >> 6;           // staging batch 0..3
    int k4   = (tid & 63) * 4;     // staging unit offset
    int bg_s = cid*4 + sb;
    int cb   = tid >> 5;           // cell batch (tid<128)
    int cu   = tid & 31;           // cell unit
    int bg_c = cid*4 + cb;

    float hmx = -1e30f, cmx = -1e30f;

    float4 pf   = make_float4(0.f,0.f,0.f,0.f);
    int    flcur = 0;
    float  c_pf = 0.f, c_last = 0.f;
    int    cfl  = 0;

    if(tid < 4){ s_flag[0][tid] = 0; }
    if(tid == 0){
        mbar_init(mbF +  0, 8);
        mbar_init(mbF +  8, 8);
        mbar_init(mbF + 16, 8);
    }
    __syncthreads();
    CARRIVE(); CWAIT();     // one-time: all peers' barriers initialized

    for(int t=0; t<T_; t++){
        // (1) stage prefetched h into sh (OLD batches)
        if(flcur == 0){
            float* dst = sh + sb*272 + (k4>>5)*34 + (k4&31);
            dst[0]=pf.x; dst[1]=pf.y; dst[2]=pf.z; dst[3]=pf.w;
        }
        // (2) prefetch for step t+1 + gx for current step
        if(t+1 < T_){
            int f   = __ldg(&father[bg_s*T_ + t+1]);
            int idx = min(f, t) + 1;
            flcur = (idx == t+1) ? 2 : ((idx == t) ? 1 : 0);
            if(flcur == 0)
                pf = __ldcg((const float4*)(g_h + (size_t)idx*BH_ + bg_s*H_ + k4));
            if((tid & 63) == 0) s_flag[(t+1)&1][sb] = flcur;
        }
        float gxv[16];
        if(kidx == 0){
#pragma unroll
            for(int rj=0; rj<4; rj++){
                const float* gp = g_gx + ((size_t)t*B_ + cid*4)*G_ + grow_[rj];
#pragma unroll
                for(int b=0;b<4;b++) gxv[rj*4+b] = __ldg(gp + b*G_);
            }
        }
        __syncthreads();   // (3)

        auto dotb = [&](int b, const float* hb){
            const u64* hq = (const u64*)(hb + kidx*34);
            u64 a0=0ull, a1=0ull, a2=0ull, a3=0ull;
#pragma unroll
            for(int i=0;i<16;i++){
                u64 hh = hq[i];
                a0 = fma2(w2[     i], hh, a0);
                a1 = fma2(w2[16 + i], hh, a1);
                a2 = fma2(w2[32 + i], hh, a2);
                a3 = fma2(w2[48 + i], hh, a3);
            }
            float2 r0=unp2(a0), r1=unp2(a1), r2=unp2(a2), r3=unp2(a3);
            float q0=r0.x+r0.y, q1=r1.x+r1.y, q2=r2.x+r2.y, q3=r3.x+r3.y;
#pragma unroll
            for(int m=1;m<8;m<<=1){
                q0 += __shfl_xor_sync(0xffffffffu, q0, m);
                q1 += __shfl_xor_sync(0xffffffffu, q1, m);
                q2 += __shfl_xor_sync(0xffffffffu, q2, m);
                q3 += __shfl_xor_sync(0xffffffffu, q3, m);
            }
            if(kidx == 0){
                s_gates[b*128 + rg*4 + 0] = q0 + gxv[0*4+b] + bh[0];
                s_gates[b*128 + rg*4 + 1] = q1 + gxv[1*4+b] + bh[1];
                s_gates[b*128 + rg*4 + 2] = q2 + gxv[2*4+b] + bh[2];
                s_gates[b*128 + rg*4 + 3] = q3 + gxv[3*4+b] + bh[3];
            }
        };

        // (4) phase A: OLD (sh) + SEMI (fbuf[(t+2)%3], full-waited at step t-1)
#pragma unroll
        for(int b=0;b<4;b++){
            int fl = s_flag[t&1][b];
            if(fl == 2) continue;
            const float* hb = (fl == 0) ? (sh + b*272) : (&fbuf[(t+2)%3][0] + b*272);
            dotb(b, hb);
        }
        // (5) p2p wait: all 8 producers' step-(t-1) pushes into slot t%3
        if(t > 0){
            int slot = t % 3;
            u32 par  = (slot == 0) ? ((u32)(t/3 + 1) & 1u) : ((u32)(t/3) & 1u);
            mbar_wait(mbF + slot*8, par);
        }
        // (6) phase B: FRESH
#pragma unroll
        for(int b=0;b<4;b++){
            if(s_flag[t&1][b] != 2) continue;
            dotb(b, &fbuf[t%3][0] + b*272);
        }
        __syncthreads();   // (7)

        // (8) LSTM cell
        if(tid < 128){
            float gi = s_gates[cb*128 +      cu];
            float gf = s_gates[cb*128 + 32 + cu];
            float gg = s_gates[cb*128 + 64 + cu];
            float go = s_gates[cb*128 + 96 + cu];
            float cprev = cfl ? c_last : c_pf;
            float cv  = sigm(gf)*cprev + sigm(gi)*tanhf(gg);
            float hv2 = sigm(go)*tanhf(cv);
            c_last = cv;
            size_t o = (size_t)(t+1)*BH_ + bg_c*H_ + u0 + cu;
            __stcg(&g_h[o], hv2);
            __stcg(&g_c[o], cv);
            float mv = __ldg(&mask[bg_c*T_ + t]);
            float hm = hv2*mv;
            out[(size_t)bg_c*(T_*H_) + (size_t)t*H_ + u0 + cu] = hm;
            hmx = fmaxf(hmx, hm);
            cmx = fmaxf(cmx, cv*mv);
            if(t+1 < T_){
                u32 la = (u32)__cvta_generic_to_shared(
                    &fbuf[(t+1)%3][cb*272 + rank*34 + cu]);
#pragma unroll
                for(int r2=0;r2<8;r2++) st_cluster_f32(la, r2, hv2);
                int f   = __ldg(&father[bg_c*T_ + t+1]);
                int idx = min(f, t) + 1;
                cfl = (idx == t+1);
                if(!cfl) c_pf = __ldcg(&g_c[(size_t)idx*BH_ + bg_c*H_ + u0 + cu]);
            }
        }
        __syncthreads();   // (9) pushes + g_h stores done CTA-wide
        if(t+1 < T_ && tid < 8){
            asm volatile("fence.acq_rel.cluster;" ::: "memory");
            mbar_arrive_remote(mbF + ((t+1)%3)*8, (u32)tid);
        }
    }

    if(tid < 128){
        size_t base = (size_t)2*B_*T_*H_;
        out[base +       bg_c*H_ + u0 + cu] = hmx;   // h_max
        out[base + BH_ + bg_c*H_ + u0 + cu] = cmx;   // c_max
    }
}

extern "C" void kernel_launch(void* const* d_in, const int* in_sizes, int n_in,
                              void* d_out, int out_size)
{
    const int*   node   = (const int*)  d_in[0];
    const int*   rel    = (const int*)  d_in[1];
    const int*   father = (const int*)  d_in[2];
    const float* mask   = (const float*)d_in[3];
    const float* emb    = (const float*)d_in[4];
    const float* W_ih   = (const float*)d_in[5];
    const float* W_hh   = (const float*)d_in[6];
    const float* b_ih   = (const float*)d_in[7];
    const float* b_hh   = (const float*)d_in[8];
    const float* W_h    = (const float*)d_in[9];
    float* out = (float*)d_out;

    float *px, *pgx;
    cudaGetSymbolAddress((void**)&px,  g_x);
    cudaGetSymbolAddress((void**)&pgx, g_gx);

    embed_kernel<<<(B_*T_)/4, 128>>>(node, rel, emb);

    dim3 g1(G_/128, (B_*T_)/128);
    sgemm_nt<<<g1, 256>>>(px, W_ih, b_ih, pgx, B_*T_, G_, 256);

    scan_kernel<<<128, 256>>>(father, mask, W_hh, b_hh, out);

    dim3 g2(H_/128, (B_*T_)/128);
    sgemm_nt<<<g2, 256>>>(out, W_h, (const float*)nullptr,
                          out + (size_t)B_*T_*H_, B_*T_, H_, 256);
}

// round 7
// speedup vs baseline: 1.0427x; 1.0427x over previous
#include <cuda_runtime.h>
#include <math.h>

#define B_ 64
#define T_ 512
#define H_ 256
#define G_ 1024
#define BH_ (B_*H_)

// ---------------- static device scratch (no allocations) ----------------
__device__ float g_x [(size_t)T_*B_*256];   // x,  row m = t*64+b
__device__ float g_gx[(size_t)T_*B_*G_];    // gx, row m = t*64+b
__device__ float g_h [(size_t)(T_+1)*BH_];  // h history [(T+1), B, H]
__device__ float g_c [(size_t)(T_+1)*BH_];  // c history

typedef unsigned long long u64;
typedef unsigned int u32;

// ---------------- f32x2 helpers ----------------
__device__ __forceinline__ u64 fma2(u64 a, u64 b, u64 c){
    u64 d; asm("fma.rn.f32x2 %0, %1, %2, %3;" : "=l"(d) : "l"(a), "l"(b), "l"(c)); return d;
}
__device__ __forceinline__ u64 pack2(float x, float y){
    u64 d; asm("mov.b64 %0, {%1, %2};" : "=l"(d)
               : "r"(__float_as_uint(x)), "r"(__float_as_uint(y))); return d;
}
__device__ __forceinline__ float2 unp2(u64 v){
    u32 lo, hi; asm("mov.b64 {%0, %1}, %2;" : "=r"(lo), "=r"(hi) : "l"(v));
    return make_float2(__uint_as_float(lo), __uint_as_float(hi));
}
__device__ __forceinline__ float sigm(float x){ return 1.0f/(1.0f + __expf(-x)); }

__device__ __forceinline__ void st_cluster_f32(u32 saddr, int rank, float v){
    u32 r;
    asm volatile("mapa.shared::cluster.u32 %0, %1, %2;" : "=r"(r) : "r"(saddr), "r"(rank));
    asm volatile("st.shared::cluster.f32 [%0], %1;" :: "r"(r), "f"(v));
}

#define CARRIVE() asm volatile("barrier.cluster.arrive.aligned;" ::: "memory")
#define CWAIT()   asm volatile("barrier.cluster.wait.aligned;"   ::: "memory")

// ---------------- embedding gather + mean + concat ----------------
__global__ __launch_bounds__(128)
void embed_kernel(const int* __restrict__ node, const int* __restrict__ rel,
                  const float* __restrict__ emb)
{
    int pos  = blockIdx.x*4 + (threadIdx.x >> 5);   // pos = b*T + t
    int lane = threadIdx.x & 31;
    int b = pos >> 9, t = pos & 511;
    const float4* E = (const float4*)emb;
    int n0 = __ldg(&node[pos*2+0]);
    int n1 = __ldg(&node[pos*2+1]);
    int r0 = __ldg(&rel[pos*3+0]);
    int r1 = __ldg(&rel[pos*3+1]);
    int r2 = __ldg(&rel[pos*3+2]);
    float4 e0 = __ldg(&E[(size_t)n0*32 + lane]);
    float4 e1 = __ldg(&E[(size_t)n1*32 + lane]);
    float4 f0 = __ldg(&E[(size_t)r0*32 + lane]);
    float4 f1 = __ldg(&E[(size_t)r1*32 + lane]);
    float4 f2 = __ldg(&E[(size_t)r2*32 + lane]);
    float4 nv = make_float4(0.5f*(e0.x+e1.x), 0.5f*(e0.y+e1.y),
                            0.5f*(e0.z+e1.z), 0.5f*(e0.w+e1.w));
    const float th = (1.0f/3.0f);
    float4 rv = make_float4(th*(f0.x+f1.x+f2.x), th*(f0.y+f1.y+f2.y),
                            th*(f0.z+f1.z+f2.z), th*(f0.w+f1.w+f2.w));
    float4* xr = (float4*)(g_x + ((size_t)t*B_ + b)*256);
    xr[lane]      = nv;
    xr[32 + lane] = rv;
}

// ---------------- SGEMM (NT): C[M,N] = A[M,K] * Bw[N,K]^T (+ bias[N]) ----------------
__global__ __launch_bounds__(256, 2)
void sgemm_nt(const float* __restrict__ A, const float* __restrict__ Bw,
              const float* __restrict__ bias, float* __restrict__ C,
              int M, int N, int K)
{
    __shared__ __align__(16) float As[16][128];
    __shared__ __align__(16) float Bs[16][128];
    int tid = threadIdx.x;
    int m0 = blockIdx.y * 128;
    int n0 = blockIdx.x * 128;
    int tx = tid & 15, ty = tid >> 4;

    int r0_ = tid & 127,        kq0 = (tid >> 7);        // 0..1
    int r1_ = r0_,              kq1 = kq0 + 2;           // 2..3

    u64 acc[8][4];
#pragma unroll
    for(int i=0;i<8;i++)
#pragma unroll
        for(int j=0;j<4;j++) acc[i][j] = 0ull;

    float4 av0, av1, bv0, bv1;
    av0 = __ldg((const float4*)(A  + (size_t)(m0+r0_)*K + kq0*4));
    av1 = __ldg((const float4*)(A  + (size_t)(m0+r1_)*K + kq1*4));
    bv0 = __ldg((const float4*)(Bw + (size_t)(n0+r0_)*K + kq0*4));
    bv1 = __ldg((const float4*)(Bw + (size_t)(n0+r1_)*K + kq1*4));
    As[kq0*4+0][r0_]=av0.x; As[kq0*4+1][r0_]=av0.y; As[kq0*4+2][r0_]=av0.z; As[kq0*4+3][r0_]=av0.w;
    As[kq1*4+0][r1_]=av1.x; As[kq1*4+1][r1_]=av1.y; As[kq1*4+2][r1_]=av1.z; As[kq1*4+3][r1_]=av1.w;
    Bs[kq0*4+0][r0_]=bv0.x; Bs[kq0*4+1][r0_]=bv0.y; Bs[kq0*4+2][r0_]=bv0.z; Bs[kq0*4+3][r0_]=bv0.w;
    Bs[kq1*4+0][r1_]=bv1.x; Bs[kq1*4+1][r1_]=bv1.y; Bs[kq1*4+2][r1_]=bv1.z; Bs[kq1*4+3][r1_]=bv1.w;
    __syncthreads();

    for(int kt=0; kt<K; kt+=16){
        bool more = (kt+16 < K);
        if(more){
            av0 = __ldg((const float4*)(A  + (size_t)(m0+r0_)*K + kt+16 + kq0*4));
            av1 = __ldg((const float4*)(A  + (size_t)(m0+r1_)*K + kt+16 + kq1*4));
            bv0 = __ldg((const float4*)(Bw + (size_t)(n0+r0_)*K + kt+16 + kq0*4));
            bv1 = __ldg((const float4*)(Bw + (size_t)(n0+r1_)*K + kt+16 + kq1*4));
        }
#pragma unroll
        for(int k=0;k<16;k++){
            float4 a0 = *(const float4*)&As[k][ty*8];
            float4 a1 = *(const float4*)&As[k][ty*8+4];
            u64 b0 = *(const u64*)&Bs[k][tx*2];
            u64 b1 = *(const u64*)&Bs[k][tx*2 + 32];
            u64 b2 = *(const u64*)&Bs[k][tx*2 + 64];
            u64 b3 = *(const u64*)&Bs[k][tx*2 + 96];
            float af[8] = {a0.x,a0.y,a0.z,a0.w,a1.x,a1.y,a1.z,a1.w};
#pragma unroll
            for(int i=0;i<8;i++){
                u64 aa = pack2(af[i], af[i]);
                acc[i][0] = fma2(aa, b0, acc[i][0]);
                acc[i][1] = fma2(aa, b1, acc[i][1]);
                acc[i][2] = fma2(aa, b2, acc[i][2]);
                acc[i][3] = fma2(aa, b3, acc[i][3]);
            }
        }
        if(more){
            __syncthreads();
            As[kq0*4+0][r0_]=av0.x; As[kq0*4+1][r0_]=av0.y; As[kq0*4+2][r0_]=av0.z; As[kq0*4+3][r0_]=av0.w;
            As[kq1*4+0][r1_]=av1.x; As[kq1*4+1][r1_]=av1.y; As[kq1*4+2][r1_]=av1.z; As[kq1*4+3][r1_]=av1.w;
            Bs[kq0*4+0][r0_]=bv0.x; Bs[kq0*4+1][r0_]=bv0.y; Bs[kq0*4+2][r0_]=bv0.z; Bs[kq0*4+3][r0_]=bv0.w;
            Bs[kq1*4+0][r1_]=bv1.x; Bs[kq1*4+1][r1_]=bv1.y; Bs[kq1*4+2][r1_]=bv1.z; Bs[kq1*4+3][r1_]=bv1.w;
            __syncthreads();
        }
    }
#pragma unroll
    for(int i=0;i<8;i++){
        float* cp = C + (size_t)(m0 + ty*8 + i)*N + n0;
#pragma unroll
        for(int j=0;j<4;j++){
            float2 v = unp2(acc[i][j]);
            int col = 32*j + 2*tx;
            if(bias){
                v.x += __ldg(&bias[n0 + col    ]);
                v.y += __ldg(&bias[n0 + col + 1]);
            }
            *(float2*)(cp + col) = v;
        }
    }
}

// ---------------- serial tree-LSTM scan ----------------
// 16 clusters x 8 CTAs, 512 threads/CTA (16 warps). Cluster c: batches [4c,4c+4).
// CTA rank r: units [32r,32r+32) -> 128 gate rows. Each thread: 2 rows x 32 K
// of W_hh in regs. kidx = tid&7 (K-chunk of 32), rg = tid>>3 (0..63).
__global__ __launch_bounds__(512, 1) __cluster_dims__(8, 1, 1)
void scan_kernel(const int* __restrict__ father, const float* __restrict__ mask,
                 const float* __restrict__ W_hh, const float* __restrict__ b_hh,
                 float* __restrict__ out)
{
    __shared__ __align__(16) float sh[4*272];       // prefetched-h staging (padded)
    __shared__ __align__(16) float fbuf[3][4*272];  // DSMEM fresh-h ring
    __shared__ float s_gates[4*128];
    __shared__ int   s_flag[2][4];                  // 0=OLD 1=SEMI 2=FRESH per batch

    int tid  = threadIdx.x;
    int rank = blockIdx.x & 7;
    int cid  = blockIdx.x >> 3;
    int u0   = rank * 32;
    int kidx = tid & 7;
    int rg   = tid >> 3;          // 0..63

    // register-resident W_hh slice: 2 gate rows x 32 K-floats (16 u64 each)
    u64   w2[32];
    float bh[2];
    int   grow_[2];
#pragma unroll
    for(int rj=0; rj<2; rj++){
        int lr   = rg*2 + rj;                      // 0..127
        int grow = (lr>>5)*256 + u0 + (lr&31);
        grow_[rj] = grow;
        bh[rj]    = __ldg(&b_hh[grow]);
        const u64* Wp = (const u64*)(W_hh + (size_t)grow*256 + kidx*32);
#pragma unroll
        for(int i=0;i<16;i++) w2[rj*16+i] = __ldg(&Wp[i]);
    }

    int sb   = tid >> 6;           // staging batch 0..3 (tid<256)
    int k4   = (tid & 63) * 4;     // staging unit offset
    int bg_s = cid*4 + (sb & 3);
    int cb   = tid >> 5;           // cell batch (tid<128)
    int cu   = tid & 31;           // cell unit
    int bg_c = cid*4 + (cb & 3);

    float hmx = -1e30f, cmx = -1e30f;

    float4 pf    = make_float4(0.f,0.f,0.f,0.f);
    int    flcur = 0;
    float  c_pf = 0.f, c_last = 0.f, mv = 0.f;
    int    cfl  = 0;

    if(tid < 4){ s_flag[0][tid] = 0; }
    __syncthreads();
    CARRIVE();                                     // pairs with wait at t=0

    for(int t=0; t<T_; t++){
        // (1) stage prefetched h into sh (OLD batches; staging threads only)
        if(tid < 256 && flcur == 0){
            float* dst = sh + sb*272 + (k4>>5)*34 + (k4&31);
            dst[0]=pf.x; dst[1]=pf.y; dst[2]=pf.z; dst[3]=pf.w;
        }
        // (2) prefetches: h for step t+1; c/mask for THIS step t
        if(tid < 256 && t+1 < T_){
            int f   = __ldg(&father[bg_s*T_ + t+1]);
            int idx = min(f, t) + 1;
            flcur = (idx == t+1) ? 2 : ((idx == t) ? 1 : 0);
            if(flcur == 0)
                pf = __ldcg((const float4*)(g_h + (size_t)idx*BH_ + bg_s*H_ + k4));
            if((tid & 63) == 0) s_flag[(t+1)&1][sb] = flcur;
        }
        if(tid < 128){
            mv = __ldg(&mask[bg_c*T_ + t]);
            int f   = __ldg(&father[bg_c*T_ + t]);   // father for step t!
            int idx = min(f, t-1) + 1;               // in [0, t]
            cfl = (idx == t);                        // fresh -> c_last register
            if(!cfl) c_pf = __ldcg(&g_c[(size_t)idx*BH_ + bg_c*H_ + u0 + cu]);
        }
        float gxv[8];
        if(kidx == 0){
#pragma unroll
            for(int rj=0; rj<2; rj++){
                const float* gp = g_gx + ((size_t)t*B_ + cid*4)*G_ + grow_[rj];
#pragma unroll
                for(int b=0;b<4;b++) gxv[rj*4+b] = __ldg(gp + b*G_);
            }
        }
        __syncthreads();   // (3)

        auto dotb = [&](int b, const float* hb){
            const u64* hq = (const u64*)(hb + kidx*34);
            u64 a0=0ull, a1=0ull;
#pragma unroll
            for(int i=0;i<16;i++){
                u64 hh = hq[i];
                a0 = fma2(w2[     i], hh, a0);
                a1 = fma2(w2[16 + i], hh, a1);
            }
            float2 r0=unp2(a0), r1=unp2(a1);
            float q0=r0.x+r0.y, q1=r1.x+r1.y;
#pragma unroll
            for(int m=1;m<8;m<<=1){
                q0 += __shfl_xor_sync(0xffffffffu, q0, m);
                q1 += __shfl_xor_sync(0xffffffffu, q1, m);
            }
            if(kidx == 0){
                s_gates[b*128 + rg*2 + 0] = q0 + gxv[0*4+b] + bh[0];
                s_gates[b*128 + rg*2 + 1] = q1 + gxv[1*4+b] + bh[1];
            }
        };

        // (4) phase A: OLD (sh) + SEMI (fbuf slot pushed 2 steps ago)
#pragma unroll
        for(int b=0;b<4;b++){
            int fl = s_flag[t&1][b];
            if(fl == 2) continue;
            const float* hb = (fl == 0) ? (sh + b*272) : (&fbuf[(t+2)%3][0] + b*272);
            dotb(b, hb);
        }
        CWAIT();           // (5) acquire peers' pushes + global h stores
        // (6) phase B: FRESH (fbuf slot pushed last step)
#pragma unroll
        for(int b=0;b<4;b++){
            if(s_flag[t&1][b] != 2) continue;
            dotb(b, &fbuf[t%3][0] + b*272);
        }
        __syncthreads();   // (7)

        // (8) LSTM cell
        if(tid < 128){
            float gi = s_gates[cb*128 +      cu];
            float gf = s_gates[cb*128 + 32 + cu];
            float gg = s_gates[cb*128 + 64 + cu];
            float go = s_gates[cb*128 + 96 + cu];
            float cprev = cfl ? c_last : c_pf;
            float cv  = sigm(gf)*cprev + sigm(gi)*tanhf(gg);
            float hv2 = sigm(go)*tanhf(cv);
            c_last = cv;
            // push FIRST (critical path), bookkeeping after
            if(t+1 < T_){
                u32 la = (u32)__cvta_generic_to_shared(
                    &fbuf[(t+1)%3][cb*272 + rank*34 + cu]);
#pragma unroll
                for(int r2=0;r2<8;r2++) st_cluster_f32(la, r2, hv2);
            }
            size_t o = (size_t)(t+1)*BH_ + bg_c*H_ + u0 + cu;
            __stcg(&g_h[o], hv2);
            __stcg(&g_c[o], cv);
            float hm = hv2*mv;
            out[(size_t)bg_c*(T_*H_) + (size_t)t*H_ + u0 + cu] = hm;
            hmx = fmaxf(hmx, hm);
            cmx = fmaxf(cmx, cv*mv);
        }
        if(t < T_-1) CARRIVE();   // (9) release pushes + stores
    }

    if(tid < 128){
        size_t base = (size_t)2*B_*T_*H_;
        out[base +       bg_c*H_ + u0 + cu] = hmx;   // h_max
        out[base + BH_ + bg_c*H_ + u0 + cu] = cmx;   // c_max
    }
}

extern "C" void kernel_launch(void* const* d_in, const int* in_sizes, int n_in,
                              void* d_out, int out_size)
{
    const int*   node   = (const int*)  d_in[0];
    const int*   rel    = (const int*)  d_in[1];
    const int*   father = (const int*)  d_in[2];
    const float* mask   = (const float*)d_in[3];
    const float* emb    = (const float*)d_in[4];
    const float* W_ih   = (const float*)d_in[5];
    const float* W_hh   = (const float*)d_in[6];
    const float* b_ih   = (const float*)d_in[7];
    const float* b_hh   = (const float*)d_in[8];
    const float* W_h    = (const float*)d_in[9];
    float* out = (float*)d_out;

    float *px, *pgx;
    cudaGetSymbolAddress((void**)&px,  g_x);
    cudaGetSymbolAddress((void**)&pgx, g_gx);

    embed_kernel<<<(B_*T_)/4, 128>>>(node, rel, emb);

    dim3 g1(G_/128, (B_*T_)/128);
    sgemm_nt<<<g1, 256>>>(px, W_ih, b_ih, pgx, B_*T_, G_, 256);

    scan_kernel<<<128, 512>>>(father, mask, W_hh, b_hh, out);

    dim3 g2(H_/128, (B_*T_)/128);
    sgemm_nt<<<g2, 256>>>(out, W_h, (const float*)nullptr,
                          out + (size_t)B_*T_*H_, B_*T_, H_, 256);
}

// round 9
// speedup vs baseline: 1.1295x; 1.0832x over previous
#include <cuda_runtime.h>
#include <math.h>

#define B_ 64
#define T_ 512
#define H_ 256
#define G_ 1024
#define BH_ (B_*H_)

// ---------------- static device scratch (no allocations) ----------------
__device__ float g_x [(size_t)T_*B_*256];   // x,  row m = t*64+b
__device__ float g_gx[(size_t)T_*B_*G_];    // gx, row m = t*64+b
__device__ float g_h [(size_t)(T_+1)*BH_];  // h history [(T+1), B, H]
__device__ float g_c [(size_t)(T_+1)*BH_];  // c history

typedef unsigned long long u64;
typedef unsigned int u32;

// ---------------- f32x2 helpers ----------------
__device__ __forceinline__ u64 fma2(u64 a, u64 b, u64 c){
    u64 d; asm("fma.rn.f32x2 %0, %1, %2, %3;" : "=l"(d) : "l"(a), "l"(b), "l"(c)); return d;
}
__device__ __forceinline__ u64 pack2(float x, float y){
    u64 d; asm("mov.b64 %0, {%1, %2};" : "=l"(d)
               : "r"(__float_as_uint(x)), "r"(__float_as_uint(y))); return d;
}
__device__ __forceinline__ float2 unp2(u64 v){
    u32 lo, hi; asm("mov.b64 {%0, %1}, %2;" : "=r"(lo), "=r"(hi) : "l"(v));
    return make_float2(__uint_as_float(lo), __uint_as_float(hi));
}
__device__ __forceinline__ float sigm(float x){ return 1.0f/(1.0f + __expf(-x)); }

// ---------------- cluster / mbarrier helpers ----------------
#define CARRIVE() asm volatile("barrier.cluster.arrive.aligned;" ::: "memory")
#define CWAIT()   asm volatile("barrier.cluster.wait.aligned;"   ::: "memory")

__device__ __forceinline__ void mbar_init(u32 a, u32 cnt){
    asm volatile("mbarrier.init.shared.b64 [%0], %1;" :: "r"(a), "r"(cnt) : "memory");
}
__device__ __forceinline__ void mbar_arrive(u32 a){
    asm volatile("mbarrier.arrive.shared.b64 _, [%0];" :: "r"(a) : "memory");
}
__device__ __forceinline__ void mbar_arrive_expect(u32 a, u32 tx){
    asm volatile("mbarrier.arrive.expect_tx.shared.b64 _, [%0], %1;"
                 :: "r"(a), "r"(tx) : "memory");
}
__device__ __forceinline__ void mbar_wait(u32 a, u32 par){
    u32 done;
    asm volatile("{\n\t.reg .pred p;\n\t"
        "mbarrier.try_wait.parity.acquire.cluster.shared::cta.b64 p, [%1], %2;\n\t"
        "selp.b32 %0,1,0,p;\n\t}"
        : "=r"(done) : "r"(a), "r"(par) : "memory");
    while(!done){
        asm volatile("{\n\t.reg .pred p;\n\t"
            "mbarrier.try_wait.parity.acquire.cluster.shared::cta.b64 p, [%1], %2, 0x989680;\n\t"
            "selp.b32 %0,1,0,p;\n\t}"
            : "=r"(done) : "r"(a), "r"(par) : "memory");
    }
}
// fire-and-forget remote smem store with tx accounting on the peer's mbarrier
__device__ __forceinline__ void st_async_f32(u32 dst, u32 mbar, int rank, float v){
    u32 rd, rm;
    asm volatile("mapa.shared::cluster.u32 %0, %1, %2;" : "=r"(rd) : "r"(dst),  "r"(rank));
    asm volatile("mapa.shared::cluster.u32 %0, %1, %2;" : "=r"(rm) : "r"(mbar), "r"(rank));
    asm volatile("st.async.shared::cluster.mbarrier::complete_tx::bytes.b32 [%0], %1, [%2];"
                 :: "r"(rd), "r"(__float_as_uint(v)), "r"(rm) : "memory");
}

// ---------------- embedding gather + mean + concat ----------------
__global__ __launch_bounds__(128)
void embed_kernel(const int* __restrict__ node, const int* __restrict__ rel,
                  const float* __restrict__ emb)
{
    int pos  = blockIdx.x*4 + (threadIdx.x >> 5);   // pos = b*T + t
    int lane = threadIdx.x & 31;
    int b = pos >> 9, t = pos & 511;
    const float4* E = (const float4*)emb;
    int n0 = __ldg(&node[pos*2+0]);
    int n1 = __ldg(&node[pos*2+1]);
    int r0 = __ldg(&rel[pos*3+0]);
    int r1 = __ldg(&rel[pos*3+1]);
    int r2 = __ldg(&rel[pos*3+2]);
    float4 e0 = __ldg(&E[(size_t)n0*32 + lane]);
    float4 e1 = __ldg(&E[(size_t)n1*32 + lane]);
    float4 f0 = __ldg(&E[(size_t)r0*32 + lane]);
    float4 f1 = __ldg(&E[(size_t)r1*32 + lane]);
    float4 f2 = __ldg(&E[(size_t)r2*32 + lane]);
    float4 nv = make_float4(0.5f*(e0.x+e1.x), 0.5f*(e0.y+e1.y),
                            0.5f*(e0.z+e1.z), 0.5f*(e0.w+e1.w));
    const float th = (1.0f/3.0f);
    float4 rv = make_float4(th*(f0.x+f1.x+f2.x), th*(f0.y+f1.y+f2.y),
                            th*(f0.z+f1.z+f2.z), th*(f0.w+f1.w+f2.w));
    float4* xr = (float4*)(g_x + ((size_t)t*B_ + b)*256);
    xr[lane]      = nv;
    xr[32 + lane] = rv;
}

// ---------------- SGEMM (NT): C[M,N] = A[M,K] * Bw[N,K]^T (+ bias[N]) ----------------
__global__ __launch_bounds__(256, 2)
void sgemm_nt(const float* __restrict__ A, const float* __restrict__ Bw,
              const float* __restrict__ bias, float* __restrict__ C,
              int M, int N, int K)
{
    __shared__ __align__(16) float As[16][128];
    __shared__ __align__(16) float Bs[16][128];
    int tid = threadIdx.x;
    int m0 = blockIdx.y * 128;
    int n0 = blockIdx.x * 128;
    int tx = tid & 15, ty = tid >> 4;

    int r0_ = tid & 127,        kq0 = (tid >> 7);        // 0..1
    int r1_ = r0_,              kq1 = kq0 + 2;           // 2..3

    u64 acc[8][4];
#pragma unroll
    for(int i=0;i<8;i++)
#pragma unroll
        for(int j=0;j<4;j++) acc[i][j] = 0ull;

    float4 av0, av1, bv0, bv1;
    av0 = __ldg((const float4*)(A  + (size_t)(m0+r0_)*K + kq0*4));
    av1 = __ldg((const float4*)(A  + (size_t)(m0+r1_)*K + kq1*4));
    bv0 = __ldg((const float4*)(Bw + (size_t)(n0+r0_)*K + kq0*4));
    bv1 = __ldg((const float4*)(Bw + (size_t)(n0+r1_)*K + kq1*4));
    As[kq0*4+0][r0_]=av0.x; As[kq0*4+1][r0_]=av0.y; As[kq0*4+2][r0_]=av0.z; As[kq0*4+3][r0_]=av0.w;
    As[kq1*4+0][r1_]=av1.x; As[kq1*4+1][r1_]=av1.y; As[kq1*4+2][r1_]=av1.z; As[kq1*4+3][r1_]=av1.w;
    Bs[kq0*4+0][r0_]=bv0.x; Bs[kq0*4+1][r0_]=bv0.y; Bs[kq0*4+2][r0_]=bv0.z; Bs[kq0*4+3][r0_]=bv0.w;
    Bs[kq1*4+0][r1_]=bv1.x; Bs[kq1*4+1][r1_]=bv1.y; Bs[kq1*4+2][r1_]=bv1.z; Bs[kq1*4+3][r1_]=bv1.w;
    __syncthreads();

    for(int kt=0; kt<K; kt+=16){
        bool more = (kt+16 < K);
        if(more){
            av0 = __ldg((const float4*)(A  + (size_t)(m0+r0_)*K + kt+16 + kq0*4));
            av1 = __ldg((const float4*)(A  + (size_t)(m0+r1_)*K + kt+16 + kq1*4));
            bv0 = __ldg((const float4*)(Bw + (size_t)(n0+r0_)*K + kt+16 + kq0*4));
            bv1 = __ldg((const float4*)(Bw + (size_t)(n0+r1_)*K + kt+16 + kq1*4));
        }
#pragma unroll
        for(int k=0;k<16;k++){
            float4 a0 = *(const float4*)&As[k][ty*8];
            float4 a1 = *(const float4*)&As[k][ty*8+4];
            u64 b0 = *(const u64*)&Bs[k][tx*2];
            u64 b1 = *(const u64*)&Bs[k][tx*2 + 32];
            u64 b2 = *(const u64*)&Bs[k][tx*2 + 64];
            u64 b3 = *(const u64*)&Bs[k][tx*2 + 96];
            float af[8] = {a0.x,a0.y,a0.z,a0.w,a1.x,a1.y,a1.z,a1.w};
#pragma unroll
            for(int i=0;i<8;i++){
                u64 aa = pack2(af[i], af[i]);
                acc[i][0] = fma2(aa, b0, acc[i][0]);
                acc[i][1] = fma2(aa, b1, acc[i][1]);
                acc[i][2] = fma2(aa, b2, acc[i][2]);
                acc[i][3] = fma2(aa, b3, acc[i][3]);
            }
        }
        if(more){
            __syncthreads();
            As[kq0*4+0][r0_]=av0.x; As[kq0*4+1][r0_]=av0.y; As[kq0*4+2][r0_]=av0.z; As[kq0*4+3][r0_]=av0.w;
            As[kq1*4+0][r1_]=av1.x; As[kq1*4+1][r1_]=av1.y; As[kq1*4+2][r1_]=av1.z; As[kq1*4+3][r1_]=av1.w;
            Bs[kq0*4+0][r0_]=bv0.x; Bs[kq0*4+1][r0_]=bv0.y; Bs[kq0*4+2][r0_]=bv0.z; Bs[kq0*4+3][r0_]=bv0.w;
            Bs[kq1*4+0][r1_]=bv1.x; Bs[kq1*4+1][r1_]=bv1.y; Bs[kq1*4+2][r1_]=bv1.z; Bs[kq1*4+3][r1_]=bv1.w;
            __syncthreads();
        }
    }
#pragma unroll
    for(int i=0;i<8;i++){
        float* cp = C + (size_t)(m0 + ty*8 + i)*N + n0;
#pragma unroll
        for(int j=0;j<4;j++){
            float2 v = unp2(acc[i][j]);
            int col = 32*j + 2*tx;
            if(bias){
                v.x += __ldg(&bias[n0 + col    ]);
                v.y += __ldg(&bias[n0 + col + 1]);
            }
            *(float2*)(cp + col) = v;
        }
    }
}

// ---------------- serial tree-LSTM scan (fence-free st.async exchange) ----------------
#define RS_ 16
struct SSm {
    float fbuf[RS_][1088];   // ring: slot s holds h_mem[s mod-class], [4 batches][8ch x 34f]
    float sh[1088];          // staged global-h (deep-old)
    float s_gx[512];         // gx for current step [gb*128 + row]
    float s_gates[512];
    u64   mbar[RS_];
    int   s_flag[2][4];      // 0=GLOBAL 1=RING 2=FRESH
    int   s_sidx[2][4];      // ring slot (idx & 15)
};

__global__ __launch_bounds__(512, 1) __cluster_dims__(8, 1, 1)
void scan_kernel(const int* __restrict__ father, const float* __restrict__ mask,
                 const float* __restrict__ W_hh, const float* __restrict__ b_hh,
                 float* __restrict__ out)
{
    extern __shared__ __align__(16) char smraw[];
    SSm* S = (SSm*)smraw;

    int tid  = threadIdx.x;
    int rank = blockIdx.x & 7;
    int cid  = blockIdx.x >> 3;
    int u0   = rank * 32;
    int kidx = tid & 7;
    int rg   = tid >> 3;          // 0..63

    u32 mb0 = (u32)__cvta_generic_to_shared(&S->mbar[0]);
    u32 fb0 = (u32)__cvta_generic_to_shared(&S->fbuf[0][0]);

    // register-resident W_hh slice: 2 gate rows x 32 K-floats (16 u64 each)
    u64   w2[32];
    float bh[2];
#pragma unroll
    for(int rj=0; rj<2; rj++){
        int lr   = rg*2 + rj;
        int grow = (lr>>5)*256 + u0 + (lr&31);
        bh[rj]   = __ldg(&b_hh[grow]);
        const u64* Wp = (const u64*)(W_hh + (size_t)grow*256 + kidx*32);
#pragma unroll
        for(int i=0;i<16;i++) w2[rj*16+i] = __ldg(&Wp[i]);
    }

    int sb   = tid >> 6;           // staging batch (tid<256)
    int k4   = (tid & 63) * 4;
    int bg_s = cid*4 + (sb & 3);
    int cb   = tid >> 5;           // cell batch (tid<128)
    int cu   = tid & 31;
    int bg_c = cid*4 + (cb & 3);
    int gbp  = tid >> 7;           // gx prefetch batch 0..3
    int rowp = tid & 127;          // gx prefetch row
    int growp = (rowp>>5)*256 + u0 + (rowp&31);

    float hmx = -1e30f, cmx = -1e30f;
    float4 pf = make_float4(0.f,0.f,0.f,0.f);
    int    flcur = 0;
    float  c_pf = 0.f, c_last = 0.f, mv = 0.f;
    int    cfl  = 0;

    // ---- init mbarriers + flags ----
    if(tid == 0){
        for(int s=0;s<RS_;s++) mbar_init(mb0 + s*8, 1);
    }
    __syncthreads();
    if(tid == 0){
        mbar_arrive(mb0);                      // slot 0 phase 0: trivial completion
        for(int s=1;s<RS_;s++) mbar_arrive_expect(mb0 + s*8, 4096u);
    }
    if(tid < 4){ S->s_flag[0][tid] = 0; S->s_sidx[0][tid] = 0; }
    __syncthreads();
    CARRIVE(); CWAIT();   // peers' mbarriers armed before any st.async flies

    // gx prologue for t=0
    float gx_reg = __ldg(&g_gx[(size_t)(cid*4+gbp)*G_ + growp]);

    for(int t=0; t<T_; t++){
        // periodic heavyweight sync: releases old g_h stores for the deep-old path
        if((t & 7) == 0 && t){ CARRIVE(); CWAIT(); }

        // publish gx for this step, prefetch next
        S->s_gx[gbp*128 + rowp] = gx_reg;
        if(t+1 < T_)
            gx_reg = __ldg(&g_gx[(size_t)(t+1)*B_*G_ + (size_t)(cid*4+gbp)*G_ + growp]);

        // stage deep-old h (prefetched last step) into sh
        if(tid < 256 && flcur == 0){
            float* dst = S->sh + sb*272 + (k4>>5)*34 + (k4&31);
            dst[0]=pf.x; dst[1]=pf.y; dst[2]=pf.z; dst[3]=pf.w;
        }
        // prefetch h classification for step t+1
        if(tid < 256 && t+1 < T_){
            int f   = __ldg(&father[bg_s*T_ + t+1]);
            int idx = min(f, t) + 1;
            flcur = (idx == t+1) ? 2 : ((idx >= t-12) ? 1 : 0);
            if(flcur == 0)
                pf = __ldcg((const float4*)(g_h + (size_t)idx*BH_ + bg_s*H_ + k4));
            if((tid & 63) == 0){
                S->s_flag[(t+1)&1][sb] = flcur;
                S->s_sidx[(t+1)&1][sb] = idx & (RS_-1);
            }
        }
        // c/mask for THIS step (same-thread history: no fence needed)
        if(tid < 128){
            mv = __ldg(&mask[bg_c*T_ + t]);
            int f   = __ldg(&father[bg_c*T_ + t]);
            int idx = min(f, t-1) + 1;
            cfl = (idx == t);
            if(!cfl) c_pf = __ldcg(&g_c[(size_t)idx*BH_ + bg_c*H_ + u0 + cu]);
        }
        __syncthreads();   // (3)

        auto dotb = [&](int b, const float* hb){
            const u64* hq = (const u64*)(hb + kidx*34);
            u64 a0=0ull, a1=0ull;
#pragma unroll
            for(int i=0;i<16;i++){
                u64 hh = hq[i];
                a0 = fma2(w2[     i], hh, a0);
                a1 = fma2(w2[16 + i], hh, a1);
            }
            float2 r0=unp2(a0), r1=unp2(a1);
            float q0=r0.x+r0.y, q1=r1.x+r1.y;
#pragma unroll
            for(int m=1;m<8;m<<=1){
                q0 += __shfl_xor_sync(0xffffffffu, q0, m);
                q1 += __shfl_xor_sync(0xffffffffu, q1, m);
            }
            if(kidx == 0){
                S->s_gates[b*128 + rg*2 + 0] = q0 + S->s_gx[b*128 + rg*2 + 0] + bh[0];
                S->s_gates[b*128 + rg*2 + 1] = q1 + S->s_gx[b*128 + rg*2 + 1] + bh[1];
            }
        };

        // phase A: GLOBAL (sh) + RING (older slots, already visible)
#pragma unroll
        for(int b=0;b<4;b++){
            int fl = S->s_flag[t&1][b];
            if(fl == 2) continue;
            const float* hb = (fl == 0) ? (S->sh + b*272)
                                        : (&S->fbuf[S->s_sidx[t&1][b]][0] + b*272);
            dotb(b, hb);
        }
        // wait current slot: all 8 producers' h_mem[t] pushes (tx-counted, no fence)
        if(t) mbar_wait(mb0 + (t & (RS_-1))*8, (u32)((t >> 4) & 1));
        // phase B: FRESH
#pragma unroll
        for(int b=0;b<4;b++){
            if(S->s_flag[t&1][b] != 2) continue;
            dotb(b, &S->fbuf[t & (RS_-1)][0] + b*272);
        }
        __syncthreads();   // (7)
        // re-arm current slot for its use 16 steps from now
        if(tid == 0) mbar_arrive_expect(mb0 + (t & (RS_-1))*8, 4096u);

        // LSTM cell
        if(tid < 128){
            float gi = S->s_gates[cb*128 +      cu];
            float gf = S->s_gates[cb*128 + 32 + cu];
            float gg = S->s_gates[cb*128 + 64 + cu];
            float go = S->s_gates[cb*128 + 96 + cu];
            float cprev = cfl ? c_last : c_pf;
            float cv  = sigm(gf)*cprev + sigm(gi)*tanhf(gg);
            float hv2 = sigm(go)*tanhf(cv);
            c_last = cv;
            if(t+1 < T_){
                u32 dst  = fb0 + (u32)((((t+1)&(RS_-1))*1088 + cb*272 + rank*34 + cu)*4);
                u32 mbsl = mb0 + (u32)(((t+1)&(RS_-1))*8);
#pragma unroll
                for(int r2=0;r2<8;r2++) st_async_f32(dst, mbsl, r2, hv2);
            }
            size_t o = (size_t)(t+1)*BH_ + bg_c*H_ + u0 + cu;
            __stcg(&g_h[o], hv2);
            __stcg(&g_c[o], cv);
            float hm = hv2*mv;
            out[(size_t)bg_c*(T_*H_) + (size_t)t*H_ + u0 + cu] = hm;
            hmx = fmaxf(hmx, hm);
            cmx = fmaxf(cmx, cv*mv);
        }
    }

    if(tid < 128){
        size_t base = (size_t)2*B_*T_*H_;
        out[base +       bg_c*H_ + u0 + cu] = hmx;   // h_max
        out[base + BH_ + bg_c*H_ + u0 + cu] = cmx;   // c_max
    }
}

extern "C" void kernel_launch(void* const* d_in, const int* in_sizes, int n_in,
                              void* d_out, int out_size)
{
    const int*   node   = (const int*)  d_in[0];
    const int*   rel    = (const int*)  d_in[1];
    const int*   father = (const int*)  d_in[2];
    const float* mask   = (const float*)d_in[3];
    const float* emb    = (const float*)d_in[4];
    const float* W_ih   = (const float*)d_in[5];
    const float* W_hh   = (const float*)d_in[6];
    const float* b_ih   = (const float*)d_in[7];
    const float* b_hh   = (const float*)d_in[8];
    const float* W_h    = (const float*)d_in[9];
    float* out = (float*)d_out;

    float *px, *pgx;
    cudaGetSymbolAddress((void**)&px,  g_x);
    cudaGetSymbolAddress((void**)&pgx, g_gx);

    embed_kernel<<<(B_*T_)/4, 128>>>(node, rel, emb);

    dim3 g1(G_/128, (B_*T_)/128);
    sgemm_nt<<<g1, 256>>>(px, W_ih, b_ih, pgx, B_*T_, G_, 256);

    cudaFuncSetAttribute(scan_kernel, cudaFuncAttributeMaxDynamicSharedMemorySize,
                         (int)sizeof(SSm));
    scan_kernel<<<128, 512, sizeof(SSm)>>>(father, mask, W_hh, b_hh, out);

    dim3 g2(H_/128, (B_*T_)/128);
    sgemm_nt<<<g2, 256>>>(out, W_h, (const float*)nullptr,
                          out + (size_t)B_*T_*H_, B_*T_, H_, 256);
}